// round 13
// baseline (speedup 1.0000x reference)
#include <cuda_runtime.h>

#define C    5
#define NPC  400
#define NN   (C*NPC)     // 2000
#define DF   64
#define HH   256
#define DOUT 64
#define EPC  12800
#define NE   (C*EPC)     // 64000
#define PAIRS 1999000LL
#define CAP  128
#define NB   296         // 2 blocks per SM on 148-SM GB300 -> all co-resident

// ---------------- scratch (static, no allocation) ----------------
__device__ unsigned long long g_bucket[NN*CAP];   // {row, w} packed
__device__ int   g_count[NN];     // zeroed by phase D for next replay (zero at load)
__device__ float g_degsum[NN];    // ditto
__device__ float g_XW1[NN*HH];
__device__ float g_XW2[NN*DOUT];
__device__ __align__(16) float g_a[NN];
__device__ __align__(16) float g_b[NN];
__device__ float g_Ea[NN];        // exp(off - alpha*invs)
__device__ float g_Fb[NN];        // exp(off - beta *invs)
__device__ int   g_barArrive;     // zero-init; reset each barrier
__device__ int   g_barGen;        // monotonic generation counter

// ---------------- device-wide generation barrier (no CCTL storm) ----------------
__device__ __forceinline__ void gbar() {
    __syncthreads();
    if (threadIdx.x == 0) {
        int gen;
        asm volatile("ld.acquire.gpu.s32 %0, [%1];" : "=r"(gen) : "l"(&g_barGen));
        int old;
        asm volatile("atom.acq_rel.gpu.add.s32 %0, [%1], %2;"
                     : "=r"(old) : "l"(&g_barArrive), "r"(1) : "memory");
        if (old == NB - 1) {
            asm volatile("st.relaxed.gpu.s32 [%0], %1;" :: "l"(&g_barArrive), "r"(0) : "memory");
            asm volatile("st.release.gpu.s32 [%0], %1;" :: "l"(&g_barGen), "r"(gen + 1) : "memory");
        } else {
            int cur;
            do {
                asm volatile("ld.relaxed.gpu.s32 %0, [%1];" : "=r"(cur) : "l"(&g_barGen));
            } while (cur == gen);
            asm volatile("ld.acquire.gpu.s32 %0, [%1];" : "=r"(cur) : "l"(&g_barGen));
        }
    }
    __syncthreads();
}

// ---------------- shared-memory overlays ----------------
struct SmemA { float sx[8][DF]; };
struct SmemB { int scnt[4]; float sdn[4]; int ssr[4*CAP]; float ssn[4*CAP];
               float sh[4][HH]; float sred[1024]; };
struct SmemC { int sr[2][128]; float sn[2][128]; float sacc[2][128];
               float ra[2][2], rb[2][2]; };
struct SmemD { float rA[8], rB[8], sc[8]; double wqx[24]; float fin[2]; };
union SmemU { SmemA a; SmemB b; SmemC c; SmemD d; };

__global__ void __launch_bounds__(256, 2)
mega(const int* __restrict__ ei, const float* __restrict__ ew,
     const float* __restrict__ x, const float* __restrict__ W1,
     const float* __restrict__ b1, const float* __restrict__ W2,
     const float* __restrict__ b2, const float* __restrict__ Watt,
     const float* __restrict__ batt, float* __restrict__ out) {
    int bid = blockIdx.x, tid = threadIdx.x;
    int lane = tid & 31;
    __shared__ SmemU S;

    // ================= Phase A: edge bucketing (units 0..124) + gemm1 (units 125..374) ========
    for (int u = bid; u < 375; u += NB) {
        if (u < 125) {
            int c = u / 25;
            int eo = (u % 25) * 512 + tid;
            const int* base = ei + c * 2 * EPC;
            const float* ewc = ew + c * EPC;
            #pragma unroll
            for (int k = 0; k < 2; k++) {
                int e = eo + k * 256;
                int row = base[e];
                int col = base[EPC + e];
                float w = ewc[e];
                int g = c * NPC + col;
                atomicAdd(&g_degsum[g], w);
                int slot = atomicAdd(&g_count[g], 1);
                if (slot < CAP)
                    g_bucket[g * CAP + slot] =
                        ((unsigned long long)(unsigned)row << 32) |
                        (unsigned long long)__float_as_uint(w);
            }
        } else {
            int b = u - 125;                 // 0..249
            int c = b / 50, n0l = (b % 50) * 8;
            const float* xc = x + (c * NPC + n0l) * DF;
            for (int i = tid; i < 8 * DF; i += 256)
                S.a.sx[i / DF][i % DF] = xc[i];
            __syncthreads();
            const float* Wc = W1 + c * DF * HH;
            float acc[8] = {0,0,0,0,0,0,0,0};
            #pragma unroll 4
            for (int k = 0; k < DF; k++) {
                float wv = Wc[k * HH + tid];
                #pragma unroll
                for (int m = 0; m < 8; m++) acc[m] += S.a.sx[m][k] * wv;
            }
            #pragma unroll
            for (int m = 0; m < 8; m++)
                g_XW1[(c * NPC + n0l + m) * HH + tid] = acc[m];
            __syncthreads();
        }
    }
    gbar();

    // ================= Phase B: gather1 + b1 + relu + gemm2 (500 units of 4 nodes) =============
    for (int u = bid; u < 500; u += NB) {
        int n0 = u * 4;
        int c = n0 / NPC, cbase = c * NPC;

        if (tid < 4) {
            int cnt = __ldcg(&g_count[n0 + tid]); if (cnt > CAP) cnt = CAP;
            S.b.scnt[tid] = cnt;
            S.b.sdn[tid] = rsqrtf(1.0f + __ldcg(&g_degsum[n0 + tid]));
        }
        __syncthreads();

        for (int idx = tid; idx < 4 * CAP; idx += 256) {
            int m = idx >> 7, s = idx & (CAP - 1);
            if (s < S.b.scnt[m]) {
                unsigned long long pk = __ldcg(&g_bucket[(n0 + m) * CAP + s]);
                int row = (int)(pk >> 32);
                float w = __uint_as_float((unsigned)pk);
                S.b.ssr[idx] = row;
                S.b.ssn[idx] = rsqrtf(1.0f + __ldcg(&g_degsum[cbase + row])) * w * S.b.sdn[m];
            }
        }
        __syncthreads();

        float bb = b1[c * HH + tid];
        for (int m = 0; m < 4; m++) {
            float dn = S.b.sdn[m];
            float acc = dn * dn * g_XW1[(n0 + m) * HH + tid];
            int cnt = S.b.scnt[m];
            const int* pr = S.b.ssr + m * CAP;
            const float* pn = S.b.ssn + m * CAP;
            #pragma unroll 4
            for (int e = 0; e < cnt; e++)
                acc += pn[e] * g_XW1[(cbase + pr[e]) * HH + tid];
            S.b.sh[m][tid] = fmaxf(acc + bb, 0.0f);
        }
        __syncthreads();

        int q = tid >> 6, f = tid & 63;
        const float* Wc = W2 + c * HH * DOUT + q * 64 * DOUT;
        float p0 = 0, p1 = 0, p2 = 0, p3 = 0;
        #pragma unroll 8
        for (int kk = 0; kk < 64; kk++) {
            int k = q * 64 + kk;
            float wv = Wc[kk * DOUT + f];
            p0 += S.b.sh[0][k] * wv; p1 += S.b.sh[1][k] * wv;
            p2 += S.b.sh[2][k] * wv; p3 += S.b.sh[3][k] * wv;
        }
        S.b.sred[q * 256 + 0 * 64 + f] = p0;
        S.b.sred[q * 256 + 1 * 64 + f] = p1;
        S.b.sred[q * 256 + 2 * 64 + f] = p2;
        S.b.sred[q * 256 + 3 * 64 + f] = p3;
        __syncthreads();

        int m = tid >> 6;
        float v = S.b.sred[0 * 256 + m * 64 + f] + S.b.sred[1 * 256 + m * 64 + f]
                + S.b.sred[2 * 256 + m * 64 + f] + S.b.sred[3 * 256 + m * 64 + f];
        g_XW2[(n0 + m) * DOUT + f] = v;
        __syncthreads();
    }
    gbar();

    // ================= Phase C: gather2 + b2 + attention dots (1000 units of 2 nodes) ==========
    for (int u = bid; u < 1000; u += NB) {
        int h = tid >> 7;          // which node of the pair
        int t = tid & 127;
        int g = u * 2 + h;
        int c = g / NPC, cbase = c * NPC;

        int cnt = __ldcg(&g_count[g]); if (cnt > CAP) cnt = CAP;
        float dn = rsqrtf(1.0f + __ldcg(&g_degsum[g]));
        if (t < cnt) {
            unsigned long long pk = __ldcg(&g_bucket[g * CAP + t]);
            int row = (int)(pk >> 32);
            float w = __uint_as_float((unsigned)pk);
            S.c.sr[h][t] = row;
            S.c.sn[h][t] = rsqrtf(1.0f + __ldcg(&g_degsum[cbase + row])) * w * dn;
        }
        __syncthreads();

        int q = t >> 6, f = t & 63;
        float acc = (q == 0) ? dn * dn * g_XW2[g * DOUT + f] : 0.0f;
        for (int e = q; e < cnt; e += 2)
            acc += S.c.sn[h][e] * g_XW2[(cbase + S.c.sr[h][e]) * DOUT + f];
        S.c.sacc[h][t] = acc;
        __syncthreads();

        if (t < 64) {
            float v = S.c.sacc[h][t] + S.c.sacc[h][t + 64] + b2[c * DOUT + t];
            float pa = v * Watt[t];
            float pb = v * Watt[DOUT + t];
            #pragma unroll
            for (int o = 16; o > 0; o >>= 1) {
                pa += __shfl_down_sync(0xffffffffu, pa, o);
                pb += __shfl_down_sync(0xffffffffu, pb, o);
            }
            if ((t & 31) == 0) { S.c.ra[h][t >> 5] = pa; S.c.rb[h][t >> 5] = pb; }
        }
        __syncthreads();
        if (t == 0) {
            g_a[g] = S.c.ra[h][0] + S.c.ra[h][1];
            g_b[g] = S.c.rb[h][0] + S.c.rb[h][1];
        }
        __syncthreads();
    }
    gbar();

    // ================= Phase D: scratch re-zero (all blocks) + stats epilogue (block 0) ========
    for (int idx = bid * 256 + tid; idx < NN; idx += NB * 256) {
        g_count[idx] = 0;
        g_degsum[idx] = 0.0f;
    }
    if (bid == 0) {
        // 256 threads, 8 contiguous elements each (256*8 = 2048 >= 2000)
        int warp = tid >> 5;
        const float cc = batt[0];
        int base = tid * 8;
        float av[8], bv[8];
        if (base < NN) {   // base+8 <= 2000 always (multiples of 8)
            #pragma unroll
            for (int k = 0; k < 2; k++) {
                float4 fa = __ldcg((const float4*)(g_a + base + k * 4));
                float4 fb = __ldcg((const float4*)(g_b + base + k * 4));
                av[k*4+0] = fa.x + cc; av[k*4+1] = fa.y + cc;
                av[k*4+2] = fa.z + cc; av[k*4+3] = fa.w + cc;
                bv[k*4+0] = fb.x; bv[k*4+1] = fb.y;
                bv[k*4+2] = fb.z; bv[k*4+3] = fb.w;
            }
        } else {
            #pragma unroll
            for (int k = 0; k < 8; k++) { av[k] = 0.0f; bv[k] = 0.0f; }
        }

        // ---- means ----
        float sa = 0.0f, sb = 0.0f;
        #pragma unroll
        for (int k = 0; k < 8; k++) { sa += av[k]; sb += bv[k]; }
        #pragma unroll
        for (int o = 16; o > 0; o >>= 1) {
            sa += __shfl_down_sync(0xffffffffu, sa, o);
            sb += __shfl_down_sync(0xffffffffu, sb, o);
        }
        if (lane == 0) { S.d.rA[warp] = sa; S.d.rB[warp] = sb; }
        __syncthreads();
        float mA = 0.0f, mB = 0.0f;
        #pragma unroll
        for (int w = 0; w < 8; w++) { mA += S.d.rA[w]; mB += S.d.rB[w]; }
        mA *= (1.0f / NN); mB *= (1.0f / NN);

        // ---- center + hierarchical exclusive scan of alpha ----
        float pre[8];
        float run = 0.0f;
        #pragma unroll
        for (int k = 0; k < 8; k++) {
            av[k] = (base + k < NN) ? av[k] - mA : 0.0f;
            bv[k] = (base + k < NN) ? bv[k] - mB : 0.0f;
            pre[k] = run;
            run += av[k];
        }
        float ls = run, inc = ls;
        #pragma unroll
        for (int o = 1; o < 32; o <<= 1) {
            float tt = __shfl_up_sync(0xffffffffu, inc, o);
            if (lane >= o) inc += tt;
        }
        if (lane == 31) S.d.sc[warp] = inc;
        __syncthreads();
        float woff = 0.0f;
        #pragma unroll
        for (int w = 0; w < 8; w++) if (w < warp) woff += S.d.sc[w];
        float pbase = woff + (inc - ls);   // exclusive prefix at element `base`

        // ---- weighted sums W, Q, X ----
        float W = 0.0f, Q = 0.0f, X = 0.0f;
        #pragma unroll
        for (int k = 0; k < 8; k++) {
            float w1 = (float)(NN - 1 - (base + k));
            float jj = (float)(base + k);
            float al = av[k], be = bv[k];
            W += w1 * al + jj * be;
            Q += w1 * al * al + jj * be * be;
            X += be * (pbase + pre[k]);
        }
        #pragma unroll
        for (int o = 16; o > 0; o >>= 1) {
            W += __shfl_down_sync(0xffffffffu, W, o);
            Q += __shfl_down_sync(0xffffffffu, Q, o);
            X += __shfl_down_sync(0xffffffffu, X, o);
        }
        if (lane == 0) {
            S.d.wqx[warp] = (double)W; S.d.wqx[8 + warp] = (double)Q; S.d.wqx[16 + warp] = (double)X;
        }
        __syncthreads();
        if (tid == 0) {
            double dW = 0, dQ = 0, dX = 0;
            #pragma unroll
            for (int w = 0; w < 8; w++) { dW += S.d.wqx[w]; dQ += S.d.wqx[8 + w]; dX += S.d.wqx[16 + w]; }
            double mu = dW / (double)PAIRS;
            double var = (dQ + 2.0 * dX - (double)PAIRS * mu * mu) / (double)(PAIRS - 1);
            double invs = 1.0 / sqrt(var);
            S.d.fin[0] = (float)invs;
            S.d.fin[1] = (float)(0.5 * mu * invs);
        }
        __syncthreads();
        float invs = S.d.fin[0], off = S.d.fin[1];
        if (base < NN) {
            #pragma unroll
            for (int k = 0; k < 8; k++) {
                int idx = base + k;
                g_Ea[idx] = __expf(off - av[k] * invs);
                g_Fb[idx] = __expf(off - bv[k] * invs);
            }
        }
    }
    gbar();

    // ================= Phase E: sigmoid over all pairs (row-paired, float4 stores) =============
    for (int u = bid; u < 1000; u += NB) {
        #pragma unroll 1
        for (int r = 0; r < 2; r++) {
            int i = (r == 0) ? u : 1998 - u;
            if (r == 1 && i == u) break;      // u==999 handled once
            int cnt = NN - 1 - i;
            long long base = (long long)i * (NN - 1) - (long long)i * (i - 1) / 2;
            float Ai = g_Ea[i];
            const float* F = g_Fb + i + 1;
            float* o = out + base;

            int head = (int)((4 - (base & 3)) & 3);
            if (head > cnt) head = cnt;
            if (tid < head) {
                float e = Ai * F[tid];
                o[tid] = __fdividef(1.0f, 1.0f + e);
            }
            int rem = cnt - head;
            int nv = rem >> 2;
            for (int v = tid; v < nv; v += 256) {
                int idx = head + v * 4;
                float e0 = Ai * F[idx];
                float e1 = Ai * F[idx + 1];
                float e2 = Ai * F[idx + 2];
                float e3 = Ai * F[idx + 3];
                float4 r4;
                r4.x = __fdividef(1.0f, 1.0f + e0);
                r4.y = __fdividef(1.0f, 1.0f + e1);
                r4.z = __fdividef(1.0f, 1.0f + e2);
                r4.w = __fdividef(1.0f, 1.0f + e3);
                *(float4*)(o + idx) = r4;
            }
            int tb = head + nv * 4;
            int t = tb + tid;
            if (t < cnt) {
                float e = Ai * F[t];
                o[t] = __fdividef(1.0f, 1.0f + e);
            }
        }
    }
}

// ---------------- launch ----------------
extern "C" void kernel_launch(void* const* d_in, const int* in_sizes, int n_in,
                              void* d_out, int out_size) {
    const float* x    = (const float*)d_in[0];
    const float* ew   = (const float*)d_in[1];
    const float* W1   = (const float*)d_in[2];
    const float* b1   = (const float*)d_in[3];
    const float* W2   = (const float*)d_in[4];
    const float* b2   = (const float*)d_in[5];
    const float* Watt = (const float*)d_in[6];
    const float* batt = (const float*)d_in[7];
    const int*   ei   = (const int*)d_in[8];
    float* out = (float*)d_out;

    mega<<<NB, 256>>>(ei, ew, x, W1, b1, W2, b2, Watt, batt, out);
}

// round 16
// speedup vs baseline: 1.3095x; 1.3095x over previous
#include <cuda_runtime.h>

#define C    5
#define NPC  400
#define NN   (C*NPC)     // 2000
#define DF   64
#define HH   256
#define DOUT 64
#define EPC  12800
#define NE   (C*EPC)     // 64000
#define PAIRS 1999000LL
#define CAP  128

// ---------------- scratch (static, no allocation) ----------------
__device__ unsigned long long g_bucket[NN*CAP];   // {row, w} packed
__device__ int   g_count[NN];     // zeroed by stats epilogue of previous invocation
__device__ float g_degsum[NN];    // ditto
__device__ float g_XW1[NN*HH];
__device__ float g_XW2[NN*DOUT];
__device__ __align__(16) float g_a[NN];
__device__ __align__(16) float g_b[NN];
__device__ float g_Ea[NN];        // exp(off - alpha*invs)
__device__ float g_Fb[NN];        // exp(off - beta *invs)
__device__ int   g_sem;           // zero-initialized; reset by epilogue each call

// ================= K1: edge bucketing (blocks 0..124) + gemm1 (blocks 125..374) =================
__global__ void k1(const int* __restrict__ ei, const float* __restrict__ ew,
                   const float* __restrict__ x, const float* __restrict__ W1) {
    int bid = blockIdx.x, tid = threadIdx.x;
    if (bid < 125) {
        int c = bid / 25;
        int eo = (bid % 25) * 512 + tid;
        const int* base = ei + c * 2 * EPC;
        const float* ewc = ew + c * EPC;
        #pragma unroll
        for (int k = 0; k < 2; k++) {
            int e = eo + k * 256;
            int row = base[e];
            int col = base[EPC + e];
            float w = ewc[e];
            int g = c * NPC + col;
            atomicAdd(&g_degsum[g], w);
            int slot = atomicAdd(&g_count[g], 1);
            if (slot < CAP)
                g_bucket[g * CAP + slot] =
                    ((unsigned long long)(unsigned)row << 32) |
                    (unsigned long long)__float_as_uint(w);
        }
    } else {
        int b = bid - 125;                 // 0..249
        int c = b / 50, n0l = (b % 50) * 8;
        __shared__ float sx[8][DF];
        const float* xc = x + (c * NPC + n0l) * DF;
        for (int i = tid; i < 8 * DF; i += 256)
            sx[i / DF][i % DF] = xc[i];
        __syncthreads();
        const float* Wc = W1 + c * DF * HH;
        float acc[8] = {0,0,0,0,0,0,0,0};
        #pragma unroll 4
        for (int k = 0; k < DF; k++) {
            float wv = Wc[k * HH + tid];
            #pragma unroll
            for (int m = 0; m < 8; m++) acc[m] += sx[m][k] * wv;
        }
        #pragma unroll
        for (int m = 0; m < 8; m++)
            g_XW1[(c * NPC + n0l + m) * HH + tid] = acc[m];
    }
}

// ================= K2: gather1 + b1 + relu + gemm2 (4 nodes/block, 500 blocks, 256 thr) =========
__global__ void k2(const float* __restrict__ b1, const float* __restrict__ W2) {
    int n0 = blockIdx.x * 4;
    int c = n0 / NPC, cbase = c * NPC;
    int tid = threadIdx.x;

    __shared__ int   scnt[4];
    __shared__ float sdn[4];
    __shared__ int   ssr[4 * CAP];
    __shared__ float ssn[4 * CAP];
    __shared__ float sh[4][HH];
    __shared__ float sred[4 * 4 * 64];

    if (tid < 4) {
        int cnt = g_count[n0 + tid]; if (cnt > CAP) cnt = CAP;
        scnt[tid] = cnt;
        sdn[tid] = rsqrtf(1.0f + g_degsum[n0 + tid]);
    }
    __syncthreads();

    for (int idx = tid; idx < 4 * CAP; idx += 256) {
        int m = idx >> 7, s = idx & (CAP - 1);
        if (s < scnt[m]) {
            unsigned long long pk = g_bucket[(n0 + m) * CAP + s];
            int row = (int)(pk >> 32);
            float w = __uint_as_float((unsigned)pk);
            ssr[idx] = row;
            ssn[idx] = rsqrtf(1.0f + g_degsum[cbase + row]) * w * sdn[m];
        }
    }
    __syncthreads();

    float bb = b1[c * HH + tid];
    for (int m = 0; m < 4; m++) {
        float dn = sdn[m];
        float acc = dn * dn * g_XW1[(n0 + m) * HH + tid];
        int cnt = scnt[m];
        const int* pr = ssr + m * CAP;
        const float* pn = ssn + m * CAP;
        #pragma unroll 4
        for (int e = 0; e < cnt; e++)
            acc += pn[e] * g_XW1[(cbase + pr[e]) * HH + tid];
        sh[m][tid] = fmaxf(acc + bb, 0.0f);
    }
    __syncthreads();

    int q = tid >> 6, f = tid & 63;
    const float* Wc = W2 + c * HH * DOUT + q * 64 * DOUT;
    float p0 = 0, p1 = 0, p2 = 0, p3 = 0;
    #pragma unroll 8
    for (int kk = 0; kk < 64; kk++) {
        int k = q * 64 + kk;
        float wv = Wc[kk * DOUT + f];
        p0 += sh[0][k] * wv; p1 += sh[1][k] * wv;
        p2 += sh[2][k] * wv; p3 += sh[3][k] * wv;
    }
    sred[q * 256 + 0 * 64 + f] = p0;
    sred[q * 256 + 1 * 64 + f] = p1;
    sred[q * 256 + 2 * 64 + f] = p2;
    sred[q * 256 + 3 * 64 + f] = p3;
    __syncthreads();

    int m = tid >> 6;
    float v = sred[0 * 256 + m * 64 + f] + sred[1 * 256 + m * 64 + f]
            + sred[2 * 256 + m * 64 + f] + sred[3 * 256 + m * 64 + f];
    g_XW2[(n0 + m) * DOUT + f] = v;
}

// ================= K3: gather2 + b2 + attention dots + (last block) stats epilogue ==============
__global__ void k3(const float* __restrict__ b2, const float* __restrict__ Watt,
                   const float* __restrict__ batt) {
    int g = blockIdx.x;
    int c = g / NPC, cbase = c * NPC;
    int tid = threadIdx.x;   // 128
    int lane = tid & 31, warp = tid >> 5;

    __shared__ int   sr[CAP];
    __shared__ float sn[CAP];
    __shared__ float sacc[128];
    __shared__ float ra[2], rb[2];
    __shared__ int   s_last;

    int cnt = g_count[g]; if (cnt > CAP) cnt = CAP;
    float dn = rsqrtf(1.0f + g_degsum[g]);
    if (tid < cnt) {
        unsigned long long pk = g_bucket[g * CAP + tid];
        int row = (int)(pk >> 32);
        float w = __uint_as_float((unsigned)pk);
        sr[tid] = row;
        sn[tid] = rsqrtf(1.0f + g_degsum[cbase + row]) * w * dn;
    }
    __syncthreads();

    int q = tid >> 6, f = tid & 63;
    float acc = (q == 0) ? dn * dn * g_XW2[g * DOUT + f] : 0.0f;
    for (int e = q; e < cnt; e += 2)
        acc += sn[e] * g_XW2[(cbase + sr[e]) * DOUT + f];
    sacc[tid] = acc;
    __syncthreads();

    if (tid < 64) {
        float v = sacc[tid] + sacc[tid + 64] + b2[c * DOUT + tid];
        float pa = v * Watt[tid];
        float pb = v * Watt[DOUT + tid];
        #pragma unroll
        for (int o = 16; o > 0; o >>= 1) {
            pa += __shfl_down_sync(0xffffffffu, pa, o);
            pb += __shfl_down_sync(0xffffffffu, pb, o);
        }
        if ((tid & 31) == 0) { ra[tid >> 5] = pa; rb[tid >> 5] = pb; }
    }
    __syncthreads();
    if (tid == 0) {
        g_a[g] = ra[0] + ra[1];
        g_b[g] = rb[0] + rb[1];
        // RELEASE-only arrival: orders the two stores above for any acquirer,
        // WITHOUT acquire semantics (no per-block L1 invalidate, no CCTL).
        int old;
        asm volatile("atom.release.gpu.add.s32 %0, [%1], %2;"
                     : "=r"(old) : "l"(&g_sem), "r"(1) : "memory");
        s_last = (old == NN - 1);
        if (s_last) {
            // Single acquire in the ONE epilogue block: synchronizes with all
            // 2000 release-RMWs on g_sem -> all g_a/g_b stores visible.
            int tmp;
            asm volatile("ld.acquire.gpu.s32 %0, [%1];" : "=r"(tmp) : "l"(&g_sem) : "memory");
        }
    }
    __syncthreads();
    if (!s_last) return;

    // ---------------- stats epilogue (only the last block runs this) ----------------
    __shared__ float  s_rA[4], s_rB[4];
    __shared__ float  s_sc[4];
    __shared__ double s_wqx[12];
    __shared__ float  s_fin[2];

    const float cc = batt[0];
    int base = tid * 16;
    float av[16], bv[16];
    if (base < NN) {   // 124*16+16 = 2000, never straddles
        #pragma unroll
        for (int k = 0; k < 4; k++) {
            float4 fa = __ldcg((const float4*)(g_a + base + k * 4));
            float4 fb = __ldcg((const float4*)(g_b + base + k * 4));
            av[k*4+0] = fa.x + cc; av[k*4+1] = fa.y + cc;
            av[k*4+2] = fa.z + cc; av[k*4+3] = fa.w + cc;
            bv[k*4+0] = fb.x; bv[k*4+1] = fb.y;
            bv[k*4+2] = fb.z; bv[k*4+3] = fb.w;
        }
    } else {
        #pragma unroll
        for (int k = 0; k < 16; k++) { av[k] = 0.0f; bv[k] = 0.0f; }
    }

    // ---- means ----
    float sa = 0.0f, sb = 0.0f;
    #pragma unroll
    for (int k = 0; k < 16; k++) { sa += av[k]; sb += bv[k]; }
    #pragma unroll
    for (int o = 16; o > 0; o >>= 1) {
        sa += __shfl_down_sync(0xffffffffu, sa, o);
        sb += __shfl_down_sync(0xffffffffu, sb, o);
    }
    if (lane == 0) { s_rA[warp] = sa; s_rB[warp] = sb; }
    __syncthreads();
    float mA = (s_rA[0] + s_rA[1] + s_rA[2] + s_rA[3]) * (1.0f / NN);
    float mB = (s_rB[0] + s_rB[1] + s_rB[2] + s_rB[3]) * (1.0f / NN);

    // ---- center + local exclusive scan of alpha ----
    float pre[16];
    float run = 0.0f;
    #pragma unroll
    for (int k = 0; k < 16; k++) {
        av[k] = (base + k < NN) ? av[k] - mA : 0.0f;
        bv[k] = (base + k < NN) ? bv[k] - mB : 0.0f;
        pre[k] = run;
        run += av[k];
    }
    float ls = run, inc = ls;
    #pragma unroll
    for (int o = 1; o < 32; o <<= 1) {
        float t = __shfl_up_sync(0xffffffffu, inc, o);
        if (lane >= o) inc += t;
    }
    if (lane == 31) s_sc[warp] = inc;
    __syncthreads();
    float woff = 0.0f;
    #pragma unroll
    for (int w = 0; w < 4; w++) if (w < warp) woff += s_sc[w];
    float pbase = woff + (inc - ls);   // exclusive prefix at element `base`

    // ---- weighted sums W, Q, X ----
    float W = 0.0f, Q = 0.0f, X = 0.0f;
    #pragma unroll
    for (int k = 0; k < 16; k++) {
        float w1 = (float)(NN - 1 - (base + k));
        float jj = (float)(base + k);
        float al = av[k], be = bv[k];
        W += w1 * al + jj * be;
        Q += w1 * al * al + jj * be * be;
        X += be * (pbase + pre[k]);
    }
    #pragma unroll
    for (int o = 16; o > 0; o >>= 1) {
        W += __shfl_down_sync(0xffffffffu, W, o);
        Q += __shfl_down_sync(0xffffffffu, Q, o);
        X += __shfl_down_sync(0xffffffffu, X, o);
    }
    if (lane == 0) {
        s_wqx[warp] = (double)W; s_wqx[4 + warp] = (double)Q; s_wqx[8 + warp] = (double)X;
    }
    __syncthreads();
    if (tid == 0) {
        double dW = s_wqx[0] + s_wqx[1] + s_wqx[2] + s_wqx[3];
        double dQ = s_wqx[4] + s_wqx[5] + s_wqx[6] + s_wqx[7];
        double dX = s_wqx[8] + s_wqx[9] + s_wqx[10] + s_wqx[11];
        double mu = dW / (double)PAIRS;
        double var = (dQ + 2.0 * dX - (double)PAIRS * mu * mu) / (double)(PAIRS - 1);
        double invs = 1.0 / sqrt(var);
        s_fin[0] = (float)invs;
        s_fin[1] = (float)(0.5 * mu * invs);
        g_sem = 0;                       // reset for next graph replay
    }
    __syncthreads();
    float invs = s_fin[0], off = s_fin[1];
    if (base < NN) {
        #pragma unroll
        for (int k = 0; k < 16; k++) {
            int idx = base + k;
            g_Ea[idx] = __expf(off - av[k] * invs);
            g_Fb[idx] = __expf(off - bv[k] * invs);
            g_count[idx] = 0;
            g_degsum[idx] = 0.0f;
        }
    }
}

// ================= K5: sigmoid over all pairs (row-paired for balance, float4 stores) ===========
__global__ void k5(float* __restrict__ out) {
    int bid = blockIdx.x;           // 0..999
    #pragma unroll 1
    for (int r = 0; r < 2; r++) {
        int i = (r == 0) ? bid : 1998 - bid;
        if (r == 1 && i == bid) break;
        int cnt = NN - 1 - i;
        long long base = (long long)i * (NN - 1) - (long long)i * (i - 1) / 2;
        float Ai = g_Ea[i];
        const float* F = g_Fb + i + 1;
        float* o = out + base;

        int head = (int)((4 - (base & 3)) & 3);
        if (head > cnt) head = cnt;
        if (threadIdx.x < head) {
            float e = Ai * F[threadIdx.x];
            o[threadIdx.x] = __fdividef(1.0f, 1.0f + e);
        }
        int rem = cnt - head;
        int nv = rem >> 2;
        for (int v = threadIdx.x; v < nv; v += blockDim.x) {
            int idx = head + v * 4;
            float e0 = Ai * F[idx];
            float e1 = Ai * F[idx + 1];
            float e2 = Ai * F[idx + 2];
            float e3 = Ai * F[idx + 3];
            float4 r4;
            r4.x = __fdividef(1.0f, 1.0f + e0);
            r4.y = __fdividef(1.0f, 1.0f + e1);
            r4.z = __fdividef(1.0f, 1.0f + e2);
            r4.w = __fdividef(1.0f, 1.0f + e3);
            *(float4*)(o + idx) = r4;
        }
        int tb = head + nv * 4;
        int t = tb + (int)threadIdx.x;
        if (t < cnt) {
            float e = Ai * F[t];
            o[t] = __fdividef(1.0f, 1.0f + e);
        }
    }
}

// ---------------- launch ----------------
extern "C" void kernel_launch(void* const* d_in, const int* in_sizes, int n_in,
                              void* d_out, int out_size) {
    const float* x    = (const float*)d_in[0];
    const float* ew   = (const float*)d_in[1];
    const float* W1   = (const float*)d_in[2];
    const float* b1   = (const float*)d_in[3];
    const float* W2   = (const float*)d_in[4];
    const float* b2   = (const float*)d_in[5];
    const float* Watt = (const float*)d_in[6];
    const float* batt = (const float*)d_in[7];
    const int*   ei   = (const int*)d_in[8];
    float* out = (float*)d_out;

    k1<<<375, 256>>>(ei, ew, x, W1);
    k2<<<500, 256>>>(b1, W2);
    k3<<<NN, 128>>>(b2, Watt, batt);
    k5<<<1000, 256>>>(out);
}